// round 1
// baseline (speedup 1.0000x reference)
#include <cuda_runtime.h>
#include <math.h>

#define TT 50
#define NB 2048
#define NS 32
#define NC 16
#define NN 48
#define LDQ 52   // row stride (floats) for 48-wide padded matrices, float4-aligned
#define LDF 52
#define LDV 33   // V row stride (conflict-free both orientations)
#define LDK 36
#define NTHREADS 384

// Scratch for feedback gains (sanctioned __device__ global scratch)
__device__ float g_K[(size_t)TT * NB * NC * NS];
__device__ float g_k[(size_t)TT * NB * NC];

// ---------------------------------------------------------------------------
// factor + value-function update.
// On entry: sQ holds Qm (48x48, row-major, stride LDQ), sqv holds qv (48).
// Computes K,k = -Quu^{-1} [Qux | qu], stores them to global scratch at step t,
// then V = sym(Qxx + Qxu K), v = qx + Qxu k  (exact-cancellation form).
// ---------------------------------------------------------------------------
__device__ __forceinline__ void factor_update(
    int t, int b, int tid,
    float* sQ, float* sqv, float* sK, float* skv, float* sdi,
    float* sV, float* sv, float* sW)
{
    // ---- Cholesky of Quu (in-place, lower, inside sQ[32..47][32..47]) ----
    #pragma unroll 1
    for (int k = 0; k < NC; ++k) {
        if (tid == 0) {
            float d = sqrtf(sQ[(NS + k) * LDQ + NS + k]);
            sdi[k] = 1.0f / d;
        }
        __syncthreads();
        if (tid > k && tid < NC)
            sQ[(NS + tid) * LDQ + NS + k] *= sdi[k];
        __syncthreads();
        if (tid < 256) {
            int i = tid >> 4, j = tid & 15;
            if (j > k && i >= j)
                sQ[(NS + i) * LDQ + NS + j] -=
                    sQ[(NS + i) * LDQ + NS + k] * sQ[(NS + j) * LDQ + NS + k];
        }
        __syncthreads();
    }

    // ---- Triangular solves: one thread per RHS column (32 Qux cols + qu) ----
    if (tid < NS + 1) {
        int col = tid;
        float r[NC];
        #pragma unroll
        for (int u = 0; u < NC; ++u)
            r[u] = (col < NS) ? sQ[(NS + u) * LDQ + col] : sqv[NS + u];
        // L y = rhs
        #pragma unroll
        for (int k = 0; k < NC; ++k) {
            r[k] *= sdi[k];
            #pragma unroll
            for (int i = k + 1; i < NC; ++i)
                r[i] -= sQ[(NS + i) * LDQ + NS + k] * r[k];
        }
        // L^T x = y
        #pragma unroll
        for (int k = NC - 1; k >= 0; --k) {
            r[k] *= sdi[k];
            #pragma unroll
            for (int i = 0; i < k; ++i)
                r[i] -= sQ[(NS + k) * LDQ + NS + i] * r[k];
        }
        if (col < NS) {
            #pragma unroll
            for (int u = 0; u < NC; ++u) sK[u * LDK + col] = -r[u];
        } else {
            #pragma unroll
            for (int u = 0; u < NC; ++u) skv[u] = -r[u];
        }
    }
    __syncthreads();

    // ---- Spill K,k to global scratch ----
    {
        float* gK = g_K + ((size_t)t * NB + b) * (NC * NS);
        for (int idx = tid; idx < NC * NS; idx += NTHREADS)
            gK[idx] = sK[(idx >> 5) * LDK + (idx & 31)];
        if (tid < NC)
            g_k[((size_t)t * NB + b) * NC + tid] = skv[tid];
    }

    // ---- Y = Qxx + Qxu K  (into sW) ; v' = qx + Qxu k ----
    if (tid < 256) {
        int i = tid >> 3, j0 = (tid & 7) * 4;
        float4 acc = *(float4*)&sQ[i * LDQ + j0];
        #pragma unroll
        for (int u = 0; u < NC; ++u) {
            float q = sQ[i * LDQ + NS + u];
            float4 kk = *(float4*)&sK[u * LDK + j0];
            acc.x += q * kk.x; acc.y += q * kk.y;
            acc.z += q * kk.z; acc.w += q * kk.w;
        }
        *(float4*)&sW[i * LDF + j0] = acc;
    } else if (tid < 256 + NS) {
        int i = tid - 256;
        float a = sqv[i];
        #pragma unroll
        for (int u = 0; u < NC; ++u) a += sQ[i * LDQ + NS + u] * skv[u];
        sv[i] = a;
    }
    __syncthreads();

    // ---- V = sym(Y) ----
    if (tid < 256) {
        int i = tid >> 3, j0 = (tid & 7) * 4;
        #pragma unroll
        for (int u = 0; u < 4; ++u) {
            int j = j0 + u;
            sV[i * LDV + j] = 0.5f * (sW[i * LDF + j] + sW[j * LDF + i]);
        }
    }
    // caller's loop-top __syncthreads() protects sV/sv consumers
}

__global__ __launch_bounds__(NTHREADS, 2)
void lqr_kernel(const float* __restrict__ x0,
                const float* __restrict__ Cin,
                const float* __restrict__ cin,
                const float* __restrict__ Fin,
                const float* __restrict__ fin,
                float* __restrict__ out)
{
    const int b = blockIdx.x;
    const int tid = threadIdx.x;

    __shared__ __align__(16) float sQ[NN * LDQ];
    __shared__ __align__(16) float sF[NS * LDF];
    __shared__ __align__(16) float sW[NS * LDF];
    __shared__ __align__(16) float sV[NS * LDV];
    __shared__ __align__(16) float sK[NC * LDK];
    __shared__ float skv[NC];
    __shared__ float sv[NS];
    __shared__ float sqv[NN];
    __shared__ float stmp[NS];
    __shared__ float sfv[NS];
    __shared__ float sdi[NC];
    __shared__ float sx[NN];
    __shared__ float sx2[NS];

    // =============================== BACKWARD ===============================
    // t = TT-1: Qm = C[T-1], qv = c[T-1]
    {
        const float4* Cp = (const float4*)(Cin + ((size_t)(TT - 1) * NB + b) * (NN * NN));
        for (int idx = tid; idx < (NN * NN) / 4; idx += NTHREADS) {
            float4 val = Cp[idx];
            int row = idx / 12, col = (idx % 12) * 4;
            *(float4*)&sQ[row * LDQ + col] = val;
        }
        const float* cp = cin + ((size_t)(TT - 1) * NB + b) * NN;
        if (tid < NN) sqv[tid] = cp[tid];
    }
    __syncthreads();
    factor_update(TT - 1, b, tid, sQ, sqv, sK, skv, sdi, sV, sv, sW);

    for (int t = TT - 2; t >= 0; --t) {
        __syncthreads();
        // ---- stage C_t, c_t, F_t, f_t ----
        {
            const float4* Cp = (const float4*)(Cin + ((size_t)t * NB + b) * (NN * NN));
            for (int idx = tid; idx < (NN * NN) / 4; idx += NTHREADS) {
                float4 val = Cp[idx];
                int row = idx / 12, col = (idx % 12) * 4;
                *(float4*)&sQ[row * LDQ + col] = val;
            }
            const float4* Fp = (const float4*)(Fin + ((size_t)t * NB + b) * (NS * NN));
            for (int idx = tid; idx < (NS * NN) / 4; idx += NTHREADS) {
                float4 val = Fp[idx];
                int row = idx / 12, col = (idx % 12) * 4;
                *(float4*)&sF[row * LDF + col] = val;
            }
            const float* cp = cin + ((size_t)t * NB + b) * NN;
            if (tid < NN) sqv[tid] = cp[tid];
            const float* fp = fin + ((size_t)t * NB + b) * NS;
            if (tid < NS) sfv[tid] = fp[tid];
        }
        __syncthreads();

        // ---- stmp = v + V f ----
        if (tid < NS) {
            float a = sv[tid];
            #pragma unroll
            for (int s = 0; s < NS; ++s) a += sV[tid * LDV + s] * sfv[s];
            stmp[tid] = a;
        }
        __syncthreads();

        // ---- qv = c + F^T stmp  (threads <48) and W = V @ F (threads <192) ----
        if (tid < NN) {
            float a = sqv[tid];
            #pragma unroll
            for (int s = 0; s < NS; ++s) a += sF[s * LDF + tid] * stmp[s];
            sqv[tid] = a;
        }
        if (tid < 192) {
            int i = tid / 12, jg = tid % 12, j = jg * 4;
            float4 a0 = {0.f, 0.f, 0.f, 0.f}, a1 = {0.f, 0.f, 0.f, 0.f};
            #pragma unroll
            for (int s = 0; s < NS; ++s) {
                float v0 = sV[i * LDV + s];
                float v1 = sV[(i + 16) * LDV + s];
                float4 ff = *(float4*)&sF[s * LDF + j];
                a0.x += v0 * ff.x; a0.y += v0 * ff.y; a0.z += v0 * ff.z; a0.w += v0 * ff.w;
                a1.x += v1 * ff.x; a1.y += v1 * ff.y; a1.z += v1 * ff.z; a1.w += v1 * ff.w;
            }
            *(float4*)&sW[i * LDF + j] = a0;
            *(float4*)&sW[(i + 16) * LDF + j] = a1;
        }
        __syncthreads();

        // ---- Qm = C + F^T W ----
        if (tid < 288) {
            int pr = tid / 12, jg = tid % 12, j = jg * 4;
            float4 q0 = *(float4*)&sQ[pr * LDQ + j];
            float4 q1 = *(float4*)&sQ[(pr + 24) * LDQ + j];
            #pragma unroll
            for (int s = 0; s < NS; ++s) {
                float f0 = sF[s * LDF + pr];
                float f1 = sF[s * LDF + pr + 24];
                float4 ww = *(float4*)&sW[s * LDF + j];
                q0.x += f0 * ww.x; q0.y += f0 * ww.y; q0.z += f0 * ww.z; q0.w += f0 * ww.w;
                q1.x += f1 * ww.x; q1.y += f1 * ww.y; q1.z += f1 * ww.z; q1.w += f1 * ww.w;
            }
            *(float4*)&sQ[pr * LDQ + j] = q0;
            *(float4*)&sQ[(pr + 24) * LDQ + j] = q1;
        }
        __syncthreads();

        factor_update(t, b, tid, sQ, sqv, sK, skv, sdi, sV, sv, sW);
    }

    // =============================== FORWARD ================================
    __syncthreads();
    if (tid < NS) sx[tid] = x0[(size_t)b * NS + tid];

    for (int t = 0; t < TT - 1; ++t) {
        __syncthreads();
        {
            const float* gK = g_K + ((size_t)t * NB + b) * (NC * NS);
            for (int idx = tid; idx < NC * NS; idx += NTHREADS)
                sK[(idx >> 5) * LDK + (idx & 31)] = gK[idx];
            if (tid < NC) skv[tid] = g_k[((size_t)t * NB + b) * NC + tid];
            const float4* Fp = (const float4*)(Fin + ((size_t)t * NB + b) * (NS * NN));
            for (int idx = tid; idx < (NS * NN) / 4; idx += NTHREADS) {
                float4 val = Fp[idx];
                int row = idx / 12, col = (idx % 12) * 4;
                *(float4*)&sF[row * LDF + col] = val;
            }
            if (tid < NS) sfv[tid] = fin[((size_t)t * NB + b) * NS + tid];
        }
        __syncthreads();
        // u = K x + k
        if (tid < NC) {
            float a = skv[tid];
            #pragma unroll
            for (int i = 0; i < NS; ++i) a += sK[tid * LDK + i] * sx[i];
            sx[NS + tid] = a;
        }
        __syncthreads();
        // emit tau_t, compute x_{t+1}
        if (tid < NN) out[((size_t)t * NB + b) * NN + tid] = sx[tid];
        if (tid < NS) {
            float a = sfv[tid];
            #pragma unroll
            for (int j = 0; j < NN; ++j) a += sF[tid * LDF + j] * sx[j];
            sx2[tid] = a;
        }
        __syncthreads();
        if (tid < NS) sx[tid] = sx2[tid];
    }

    // final step t = TT-1
    __syncthreads();
    {
        const float* gK = g_K + ((size_t)(TT - 1) * NB + b) * (NC * NS);
        for (int idx = tid; idx < NC * NS; idx += NTHREADS)
            sK[(idx >> 5) * LDK + (idx & 31)] = gK[idx];
        if (tid < NC) skv[tid] = g_k[((size_t)(TT - 1) * NB + b) * NC + tid];
    }
    __syncthreads();
    if (tid < NC) {
        float a = skv[tid];
        #pragma unroll
        for (int i = 0; i < NS; ++i) a += sK[tid * LDK + i] * sx[i];
        sx[NS + tid] = a;
    }
    __syncthreads();
    if (tid < NN) out[((size_t)(TT - 1) * NB + b) * NN + tid] = sx[tid];
}

extern "C" void kernel_launch(void* const* d_in, const int* in_sizes, int n_in,
                              void* d_out, int out_size) {
    // Select inputs by element count (all five are distinct) for robustness.
    const float *x0 = nullptr, *C = nullptr, *c = nullptr, *F = nullptr, *f = nullptr;
    for (int i = 0; i < n_in; ++i) {
        switch (in_sizes[i]) {
            case NB * NS:                         x0 = (const float*)d_in[i]; break; // 65536
            case TT * NB * NN * NN:               C  = (const float*)d_in[i]; break; // wouldn't fit switch? handled below
            default: break;
        }
    }
    // The big sizes exceed what a switch on literal expressions reads clearly; do explicit matching:
    for (int i = 0; i < n_in; ++i) {
        long long s = in_sizes[i];
        if (s == (long long)TT * NB * NN * NN) C = (const float*)d_in[i];
        else if (s == (long long)TT * NB * NN) c = (const float*)d_in[i];
        else if (s == (long long)(TT - 1) * NB * NS * NN) F = (const float*)d_in[i];
        else if (s == (long long)(TT - 1) * NB * NS) f = (const float*)d_in[i];
        else if (s == (long long)NB * NS) x0 = (const float*)d_in[i];
    }
    float* out = (float*)d_out;
    lqr_kernel<<<NB, NTHREADS>>>(x0, C, c, F, f, out);
}

// round 2
// speedup vs baseline: 1.2570x; 1.2570x over previous
#include <cuda_runtime.h>
#include <math.h>

#define TT 50
#define NB 2048
#define NS 32
#define NC 16
#define NN 48
#define LDQ 52
#define LDF 52
#define LDV 33
#define LDK 36
#define FULLM 0xffffffffu
#define NTHREADS 128

// Scratch for feedback gains (sanctioned __device__ global scratch)
__device__ float g_K[(size_t)TT * NB * NC * NS];
__device__ float g_k[(size_t)TT * NB * NC];

// Fused forward+backward triangular solves for two RHS vectors sharing the
// shuffle stream. a[] = lane's Cholesky column (lanes 0..15 valid), di[] = 1/L[k][k].
__device__ __forceinline__ void fwdbwd2(float* y, float* z, const float* a, const float* di)
{
    #pragma unroll
    for (int k = 0; k < 16; ++k) {
        y[k] *= di[k]; z[k] *= di[k];
        #pragma unroll
        for (int i = k + 1; i < 16; ++i) {
            float lik = __shfl_sync(FULLM, a[i], k);
            y[i] -= lik * y[k];
            z[i] -= lik * z[k];
        }
    }
    #pragma unroll
    for (int k = 15; k >= 0; --k) {
        y[k] *= di[k]; z[k] *= di[k];
        #pragma unroll
        for (int i = 0; i < k; ++i) {
            float lki = __shfl_sync(FULLM, a[k], i);
            y[i] -= lki * y[k];
            z[i] -= lki * z[k];
        }
    }
}

// Warp-0-only factor: Cholesky of Quu (16x16) in registers via shuffles,
// then solve for K (32 cols, lane-parallel) and k (fused second RHS).
// Writes sK (negated) and skv (negated). No block barriers inside.
__device__ __forceinline__ void factor_w0(int lane, const float* sQ, const float* sqv,
                                          float* sK, float* skv)
{
    float a[16], di[16];
    if (lane < 16) {
        #pragma unroll
        for (int i = 0; i < 16; ++i)
            a[i] = sQ[(NS + i) * LDQ + NS + lane];
    }
    #pragma unroll
    for (int k = 0; k < 16; ++k) {
        float akk = __shfl_sync(FULLM, a[k], k);
        float dinv = 1.0f / sqrtf(akk);
        di[k] = dinv;
        if (lane == k) {
            #pragma unroll
            for (int i = 0; i < 16; ++i)
                if (i >= k) a[i] *= dinv;
        }
        float l[16];
        float ljk = 0.0f;
        #pragma unroll
        for (int i = k + 1; i < 16; ++i) {
            l[i] = __shfl_sync(FULLM, a[i], k);
            if (lane == i) ljk = l[i];
        }
        if (lane > k && lane < 16) {
            #pragma unroll
            for (int i = k + 1; i < 16; ++i)
                if (i >= lane) a[i] -= l[i] * ljk;
        }
    }
    // K solve: lane j handles Qux column j (32 cols). z = qu (redundant per lane).
    float y[16], z[16];
    #pragma unroll
    for (int u = 0; u < 16; ++u) {
        y[u] = sQ[(NS + u) * LDQ + lane];
        z[u] = sqv[NS + u];
    }
    fwdbwd2(y, z, a, di);
    #pragma unroll
    for (int u = 0; u < 16; ++u)
        sK[u * LDK + lane] = -y[u];
    #pragma unroll
    for (int u = 0; u < 16; ++u)
        if (lane == u) skv[u] = -z[u];
}

// P3: Y = Qxx + Qxu@K -> sW ; v = qx + Qxu k -> sv ; spill K,k to global.
__device__ __forceinline__ void p3_phase(int tid, int t, int b,
                                         const float* sQ, const float* sK,
                                         const float* skv, const float* sqv,
                                         float* sW, float* sv)
{
    int i = tid & 31, jg = tid >> 5;
    int j0 = jg * 8;
    float qxu[16];
    #pragma unroll
    for (int u = 0; u < 16; ++u) qxu[u] = sQ[i * LDQ + NS + u];

    float4 acc0 = *(const float4*)&sQ[i * LDQ + j0];
    float4 acc1 = *(const float4*)&sQ[i * LDQ + j0 + 4];
    #pragma unroll
    for (int u = 0; u < 16; ++u) {
        float4 k0 = *(const float4*)&sK[u * LDK + j0];
        float4 k1 = *(const float4*)&sK[u * LDK + j0 + 4];
        float q = qxu[u];
        acc0.x += q * k0.x; acc0.y += q * k0.y; acc0.z += q * k0.z; acc0.w += q * k0.w;
        acc1.x += q * k1.x; acc1.y += q * k1.y; acc1.z += q * k1.z; acc1.w += q * k1.w;
    }
    *(float4*)&sW[i * LDF + j0] = acc0;
    *(float4*)&sW[i * LDF + j0 + 4] = acc1;

    if (tid < NS) {
        float a = sqv[i];
        #pragma unroll
        for (int u = 0; u < 16; ++u) a += qxu[u] * skv[u];
        sv[i] = a;
    }
    // spill K, k (coalesced)
    float* gK = g_K + ((size_t)t * NB + b) * (NC * NS);
    #pragma unroll
    for (int m = 0; m < 4; ++m) {
        int idx = m * NTHREADS + tid;
        gK[idx] = sK[(idx >> 5) * LDK + (idx & 31)];
    }
    if (tid < NC)
        g_k[((size_t)t * NB + b) * NC + tid] = skv[tid];
}

__global__ __launch_bounds__(NTHREADS, 5)
void lqr_kernel(const float* __restrict__ x0,
                const float* __restrict__ Cin,
                const float* __restrict__ cin,
                const float* __restrict__ Fin,
                const float* __restrict__ fin,
                float* __restrict__ out)
{
    const int b = blockIdx.x;
    const int tid = threadIdx.x;
    const int lane = tid & 31;
    const int warp = tid >> 5;

    __shared__ __align__(16) float sQ[NN * LDQ];
    __shared__ __align__(16) float sF[NS * LDF];
    __shared__ __align__(16) float sW[NS * LDF];
    __shared__ __align__(16) float sV[NS * LDV];
    __shared__ __align__(16) float sK[NC * LDK];
    __shared__ float sqv[NN], sv[NS], sfv[NS], skv[NC], sx[NN], sx2[NS];

    // =============================== BACKWARD ===============================
    // init: C[T-1] -> sQ, c[T-1] -> sqv
    {
        const float2* Cp = (const float2*)(Cin + ((size_t)(TT - 1) * NB + b) * (NN * NN));
        #pragma unroll
        for (int m = 0; m < 9; ++m) {
            int idx = m * NTHREADS + tid;
            float2 v = Cp[idx];
            *(float2*)&sQ[(idx / 24) * LDQ + (idx % 24) * 2] = v;
        }
        if (tid < NN) sqv[tid] = cin[((size_t)(TT - 1) * NB + b) * NN + tid];
    }

    // prefetch registers (held by threads 32..127)
    float2 cpre[12];
    float4 fpre[4];
    float cp = 0.0f, fp = 0.0f;

    // issue prefetch for t = TT-2 (C, c, f, F)
    if (tid >= 32) {
        const int t = TT - 2;
        const float4* Fp = (const float4*)(Fin + ((size_t)t * NB + b) * (NS * NN));
        #pragma unroll
        for (int m = 0; m < 4; ++m) fpre[m] = Fp[m * 96 + (tid - 32)];
        const float2* Cp = (const float2*)(Cin + ((size_t)t * NB + b) * (NN * NN));
        #pragma unroll
        for (int m = 0; m < 12; ++m) cpre[m] = Cp[m * 96 + (tid - 32)];
        if (tid < 80) cp = cin[((size_t)t * NB + b) * NN + (tid - 32)];
        if (tid >= 96) fp = fin[((size_t)t * NB + b) * NS + (tid - 96)];
    }
    __syncthreads();

    // factor(T-1); meanwhile warps 1-3 store F_{T-2} -> sF
    if (warp == 0) {
        factor_w0(lane, sQ, sqv, sK, skv);
    } else {
        #pragma unroll
        for (int m = 0; m < 4; ++m) {
            int idx = m * 96 + (tid - 32);
            *(float4*)&sF[(idx / 12) * LDF + (idx % 12) * 4] = fpre[m];
        }
    }
    __syncthreads();
    p3_phase(tid, TT - 1, b, sQ, sK, skv, sqv, sW, sv);
    __syncthreads();
    // sym: V = 0.5*(Y + Y^T)
    {
        int i = tid & 31, jg = tid >> 5;
        #pragma unroll
        for (int jj = 0; jj < 8; ++jj) {
            int j = jg * 8 + jj;
            sV[i * LDV + j] = 0.5f * (sW[i * LDF + j] + sW[j * LDF + i]);
        }
    }
    __syncthreads();

    for (int t = TT - 2; t >= 0; --t) {
        // ---- phase a: commit prefetched C_t, c_t, f_t; issue F_{t-1} load ----
        if (tid >= 32) {
            #pragma unroll
            for (int m = 0; m < 12; ++m) {
                int idx = m * 96 + (tid - 32);
                *(float2*)&sQ[(idx / 24) * LDQ + (idx % 24) * 2] = cpre[m];
            }
            if (tid < 80) sqv[tid - 32] = cp;
            if (tid >= 96) sfv[tid - 96] = fp;
            if (t > 0) {
                const float4* Fp = (const float4*)(Fin + ((size_t)(t - 1) * NB + b) * (NS * NN));
                #pragma unroll
                for (int m = 0; m < 4; ++m) fpre[m] = Fp[m * 96 + (tid - 32)];
            }
        }
        __syncthreads(); // B1

        // ---- P1: W = V @ F  (V symmetric) ----
        {
            int i = lane, base = warp * 12;
            float4 a0 = {0.f,0.f,0.f,0.f}, a1 = a0, a2 = a0;
            #pragma unroll
            for (int s = 0; s < NS; ++s) {
                float v = sV[i * LDV + s];
                float4 f0 = *(const float4*)&sF[s * LDF + base];
                float4 f1 = *(const float4*)&sF[s * LDF + base + 4];
                float4 f2 = *(const float4*)&sF[s * LDF + base + 8];
                a0.x += v * f0.x; a0.y += v * f0.y; a0.z += v * f0.z; a0.w += v * f0.w;
                a1.x += v * f1.x; a1.y += v * f1.y; a1.z += v * f1.z; a1.w += v * f1.w;
                a2.x += v * f2.x; a2.y += v * f2.y; a2.z += v * f2.z; a2.w += v * f2.w;
            }
            *(float4*)&sW[i * LDF + base] = a0;
            *(float4*)&sW[i * LDF + base + 4] = a1;
            *(float4*)&sW[i * LDF + base + 8] = a2;
        }
        __syncthreads(); // B2

        // ---- P2: Qm = C + F^T W (96 thr) ; qv = c + F^T v + W^T f (32 thr) ----
        if (tid < 96) {
            int c4 = tid % 12, r0 = tid / 12;
            float4 q[6];
            #pragma unroll
            for (int u = 0; u < 6; ++u)
                q[u] = *(const float4*)&sQ[(r0 + 8 * u) * LDQ + c4 * 4];
            #pragma unroll
            for (int s = 0; s < NS; ++s) {
                float4 w = *(const float4*)&sW[s * LDF + c4 * 4];
                #pragma unroll
                for (int u = 0; u < 6; ++u) {
                    float fv = sF[s * LDF + r0 + 8 * u];
                    q[u].x += fv * w.x; q[u].y += fv * w.y;
                    q[u].z += fv * w.z; q[u].w += fv * w.w;
                }
            }
            #pragma unroll
            for (int u = 0; u < 6; ++u)
                *(float4*)&sQ[(r0 + 8 * u) * LDQ + c4 * 4] = q[u];
        } else {
            int t0 = tid - 96;
            float a = sqv[t0];
            #pragma unroll
            for (int s = 0; s < NS; ++s)
                a += sF[s * LDF + t0] * sv[s] + sW[s * LDF + t0] * sfv[s];
            float a2v = 0.0f;
            if (t0 < 16) {
                a2v = sqv[NS + t0];
                #pragma unroll
                for (int s = 0; s < NS; ++s)
                    a2v += sF[s * LDF + NS + t0] * sv[s] + sW[s * LDF + NS + t0] * sfv[s];
            }
            sqv[t0] = a;
            if (t0 < 16) sqv[NS + t0] = a2v;
        }
        // issue C_{t-1}, c_{t-1}, f_{t-1} prefetch (regs free after phase a)
        if (t > 0 && tid >= 32) {
            const float2* Cp = (const float2*)(Cin + ((size_t)(t - 1) * NB + b) * (NN * NN));
            #pragma unroll
            for (int m = 0; m < 12; ++m) cpre[m] = Cp[m * 96 + (tid - 32)];
            if (tid < 80) cp = cin[((size_t)(t - 1) * NB + b) * NN + (tid - 32)];
            if (tid >= 96) fp = fin[((size_t)(t - 1) * NB + b) * NS + (tid - 96)];
        }
        __syncthreads(); // B3

        // ---- factor (warp 0) ; warps 1-3 commit F_{t-1} -> sF ----
        if (warp == 0) {
            factor_w0(lane, sQ, sqv, sK, skv);
        } else if (t > 0) {
            #pragma unroll
            for (int m = 0; m < 4; ++m) {
                int idx = m * 96 + (tid - 32);
                *(float4*)&sF[(idx / 12) * LDF + (idx % 12) * 4] = fpre[m];
            }
        }
        __syncthreads(); // B4

        p3_phase(tid, t, b, sQ, sK, skv, sqv, sW, sv);
        __syncthreads(); // B5

        {
            int i = tid & 31, jg = tid >> 5;
            #pragma unroll
            for (int jj = 0; jj < 8; ++jj) {
                int j = jg * 8 + jj;
                sV[i * LDV + j] = 0.5f * (sW[i * LDF + j] + sW[j * LDF + i]);
            }
        }
        __syncthreads(); // B6 (also protects sQ overwrite at next phase a)
    }

    // =============================== FORWARD ================================
    if (tid < NS) sx[tid] = x0[(size_t)b * NS + tid];

    float kreg[4];
    float4 freg[3];
    float fsreg = 0.0f, kvreg = 0.0f;
    {
        const float* gK = g_K + ((size_t)0 * NB + b) * (NC * NS);
        #pragma unroll
        for (int m = 0; m < 4; ++m) kreg[m] = gK[m * NTHREADS + tid];
        const float4* Fp = (const float4*)(Fin + ((size_t)0 * NB + b) * (NS * NN));
        #pragma unroll
        for (int m = 0; m < 3; ++m) freg[m] = Fp[m * NTHREADS + tid];
        if (tid >= 32 && tid < 64) fsreg = fin[((size_t)0 * NB + b) * NS + (tid - 32)];
        if (tid >= 64 && tid < 80) kvreg = g_k[((size_t)0 * NB + b) * NC + (tid - 64)];
    }

    for (int t = 0; t < TT - 1; ++t) {
        #pragma unroll
        for (int m = 0; m < 4; ++m) {
            int idx = m * NTHREADS + tid;
            sK[(idx >> 5) * LDK + (idx & 31)] = kreg[m];
        }
        #pragma unroll
        for (int m = 0; m < 3; ++m) {
            int idx = m * NTHREADS + tid;
            *(float4*)&sF[(idx / 12) * LDF + (idx % 12) * 4] = freg[m];
        }
        if (tid >= 32 && tid < 64) sfv[tid - 32] = fsreg;
        if (tid >= 64 && tid < 80) skv[tid - 64] = kvreg;
        __syncthreads(); // B1
        if (t < TT - 2) {
            const float* gK = g_K + ((size_t)(t + 1) * NB + b) * (NC * NS);
            #pragma unroll
            for (int m = 0; m < 4; ++m) kreg[m] = gK[m * NTHREADS + tid];
            const float4* Fp = (const float4*)(Fin + ((size_t)(t + 1) * NB + b) * (NS * NN));
            #pragma unroll
            for (int m = 0; m < 3; ++m) freg[m] = Fp[m * NTHREADS + tid];
            if (tid >= 32 && tid < 64) fsreg = fin[((size_t)(t + 1) * NB + b) * NS + (tid - 32)];
            if (tid >= 64 && tid < 80) kvreg = g_k[((size_t)(t + 1) * NB + b) * NC + (tid - 64)];
        }
        // u = K x + k  (warp 0, 2 lanes per output)
        if (warp == 0) {
            int u = lane & 15, h = lane >> 4;
            float acc = 0.0f;
            #pragma unroll
            for (int ii = 0; ii < 16; ++ii)
                acc += sK[u * LDK + h * 16 + ii] * sx[h * 16 + ii];
            acc += __shfl_xor_sync(FULLM, acc, 16);
            if (lane < 16) sx[NS + lane] = acc + skv[lane];
        }
        __syncthreads(); // B2
        if (tid < NN) out[((size_t)t * NB + b) * NN + tid] = sx[tid];
        if (tid >= 64 && tid < 96) {
            int s = tid - 64;
            float acc = sfv[s];
            #pragma unroll
            for (int j = 0; j < NN; ++j) acc += sF[s * LDF + j] * sx[j];
            sx2[s] = acc;
        }
        __syncthreads(); // B3
        if (tid < NS) sx[tid] = sx2[tid];
    }

    // final step t = TT-1
    {
        const float* gK = g_K + ((size_t)(TT - 1) * NB + b) * (NC * NS);
        #pragma unroll
        for (int m = 0; m < 4; ++m) {
            int idx = m * NTHREADS + tid;
            sK[(idx >> 5) * LDK + (idx & 31)] = gK[idx];
        }
        if (tid < NC) skv[tid] = g_k[((size_t)(TT - 1) * NB + b) * NC + tid];
    }
    __syncthreads();
    if (warp == 0) {
        int u = lane & 15, h = lane >> 4;
        float acc = 0.0f;
        #pragma unroll
        for (int ii = 0; ii < 16; ++ii)
            acc += sK[u * LDK + h * 16 + ii] * sx[h * 16 + ii];
        acc += __shfl_xor_sync(FULLM, acc, 16);
        if (lane < 16) sx[NS + lane] = acc + skv[lane];
    }
    __syncthreads();
    if (tid < NN) out[((size_t)(TT - 1) * NB + b) * NN + tid] = sx[tid];
}

extern "C" void kernel_launch(void* const* d_in, const int* in_sizes, int n_in,
                              void* d_out, int out_size) {
    const float *x0 = nullptr, *C = nullptr, *c = nullptr, *F = nullptr, *f = nullptr;
    for (int i = 0; i < n_in; ++i) {
        long long s = in_sizes[i];
        if (s == (long long)TT * NB * NN * NN) C = (const float*)d_in[i];
        else if (s == (long long)TT * NB * NN) c = (const float*)d_in[i];
        else if (s == (long long)(TT - 1) * NB * NS * NN) F = (const float*)d_in[i];
        else if (s == (long long)(TT - 1) * NB * NS) f = (const float*)d_in[i];
        else if (s == (long long)NB * NS) x0 = (const float*)d_in[i];
    }
    float* out = (float*)d_out;
    lqr_kernel<<<NB, NTHREADS>>>(x0, C, c, F, f, out);
}

// round 3
// speedup vs baseline: 1.3086x; 1.0410x over previous
#include <cuda_runtime.h>
#include <math.h>

#define TT 50
#define NB 2048
#define NS 32
#define NC 16
#define NN 48
#define LDQ 52
#define LDF 52
#define LDV 33
#define LDK 36
#define FULLM 0xffffffffu
#define NTHREADS 256

// smem layout (floats) in one flat array
#define SQ_SZ 2496   // 48*52
#define SF_SZ 1664   // 32*52
#define O_SQ(p)  ((p)*SQ_SZ)
#define O_SF(p)  (4992 + (p)*SF_SZ)
#define O_SW     8320
#define O_SV     9984
#define O_SK     11040
#define O_SCV(p) (11616 + (p)*48)
#define O_SFV(p) (11712 + (p)*32)
#define O_SQV    11776
#define O_SVV    11824
#define O_SKV    11856
#define O_SX     11872
#define O_SX2    11920
#define SMEM_TOT 11952
// forward-pass aliases (sW/sV regions are dead in forward)
#define O_K2(p)  (O_SW + (p)*576)
#define O_KV2(p) (O_SV + (p)*16)

__device__ float g_K[(size_t)TT * NB * NC * NS];
__device__ float g_k[(size_t)TT * NB * NC];

__device__ __forceinline__ void cp16(float* smem_dst, const float* gmem_src) {
    unsigned sa = (unsigned)__cvta_generic_to_shared(smem_dst);
    asm volatile("cp.async.cg.shared.global [%0], [%1], 16;" :: "r"(sa), "l"(gmem_src));
}
#define CP_COMMIT() asm volatile("cp.async.commit_group;")
#define CP_WAIT(n)  asm volatile("cp.async.wait_group %0;" :: "n"(n))

// triangular solves L y' = y ; L^T y'' = y'  (L in lanes 0..15 of a[], di = 1/diag)
__device__ __forceinline__ void trisolve(float* y, const float* a, const float* di)
{
    #pragma unroll
    for (int k = 0; k < 16; ++k) {
        y[k] *= di[k];
        #pragma unroll
        for (int i = k + 1; i < 16; ++i)
            y[i] -= __shfl_sync(FULLM, a[i], k) * y[k];
    }
    #pragma unroll
    for (int k = 15; k >= 0; --k) {
        y[k] *= di[k];
        #pragma unroll
        for (int i = 0; i < k; ++i)
            y[i] -= __shfl_sync(FULLM, a[k], i) * y[k];
    }
}

// Warp-0 factor: Cholesky of Quu (16x16) in registers; solve K (32 cols
// lane-parallel), then k (serial second solve, saves 16 regs).
__device__ __forceinline__ void factor_w0(int lane, const float* sQp, const float* qu,
                                          float* sK, float* skv)
{
    float a[16], di[16];
    if (lane < 16) {
        #pragma unroll
        for (int i = 0; i < 16; ++i)
            a[i] = sQp[(NS + i) * LDQ + NS + lane];
    }
    #pragma unroll
    for (int k = 0; k < 16; ++k) {
        float akk = __shfl_sync(FULLM, a[k], k);
        float dinv = rsqrtf(akk);
        di[k] = dinv;
        if (lane == k) {
            #pragma unroll
            for (int i = 0; i < 16; ++i)
                if (i >= k) a[i] *= dinv;
        }
        float l[16];
        float ljk = 0.0f;
        #pragma unroll
        for (int i = k + 1; i < 16; ++i) {
            l[i] = __shfl_sync(FULLM, a[i], k);
            if (lane == i) ljk = l[i];
        }
        if (lane > k && lane < 16) {
            #pragma unroll
            for (int i = k + 1; i < 16; ++i)
                if (i >= lane) a[i] -= l[i] * ljk;
        }
    }
    // K columns: lane j solves Qux column j
    float y[16];
    #pragma unroll
    for (int u = 0; u < 16; ++u) y[u] = sQp[(NS + u) * LDQ + lane];
    trisolve(y, a, di);
    #pragma unroll
    for (int u = 0; u < 16; ++u) sK[u * LDK + lane] = -y[u];
    // k vector (redundant across lanes)
    #pragma unroll
    for (int u = 0; u < 16; ++u) y[u] = qu[u];
    trisolve(y, a, di);
    if (lane < 16) skv[lane] = -y[lane];
}

// p3: V = Qxx + Qxu@K (written straight to sV, sym skipped — exact in infinite
// precision); v = qx + Qxu k ; spill K,k. Qxu read as Qux rows (== reference).
__device__ __forceinline__ void p3_phase(float* sm, int tid, int t, int b,
                                         const float* sQp, const float* qx)
{
    const float* sK = sm + O_SK;
    float* sV = sm + O_SV;
    int i = tid & 31, g = tid >> 5, j0 = 4 * g;
    float4 acc = *(const float4*)&sQp[i * LDQ + j0];
    #pragma unroll
    for (int u = 0; u < 16; ++u) {
        float q = sQp[(NS + u) * LDQ + i];
        float4 k4 = *(const float4*)&sK[u * LDK + j0];
        acc.x += q * k4.x; acc.y += q * k4.y; acc.z += q * k4.z; acc.w += q * k4.w;
    }
    sV[i * LDV + j0 + 0] = acc.x;
    sV[i * LDV + j0 + 1] = acc.y;
    sV[i * LDV + j0 + 2] = acc.z;
    sV[i * LDV + j0 + 3] = acc.w;
    if (tid < NS) {
        const float* skv = sm + O_SKV;
        float a = qx[i];
        #pragma unroll
        for (int u = 0; u < 16; ++u) a += sQp[(NS + u) * LDQ + i] * skv[u];
        sm[O_SVV + i] = a;
    }
    // spill
    float* gK = g_K + ((size_t)t * NB + b) * (NC * NS);
    #pragma unroll
    for (int m = 0; m < 2; ++m) {
        int idx = m * NTHREADS + tid;
        gK[idx] = sK[(idx >> 5) * LDK + (idx & 31)];
    }
    if (tid < NC)
        g_k[((size_t)t * NB + b) * NC + tid] = sm[O_SKV + tid];
}

// issue cp.async group for backward step t into buffer `buf`
__device__ __forceinline__ void issue_bwd(float* sm, int tid, int t, int b,
                                          const float* Cin, const float* cin,
                                          const float* Fin, const float* fin,
                                          int buf, bool withF)
{
    {
        const float* src = Cin + ((size_t)t * NB + b) * (NN * NN);
        float* dst = sm + O_SQ(buf);
        #pragma unroll
        for (int m = 0; m < 3; ++m) {
            int idx = m * NTHREADS + tid;
            if (idx < 576) {
                int row = idx / 12, c4 = idx % 12;
                cp16(dst + row * LDQ + c4 * 4, src + idx * 4);
            }
        }
    }
    if (tid < 12)
        cp16(sm + O_SCV(buf) + tid * 4, cin + ((size_t)t * NB + b) * NN + tid * 4);
    if (withF) {
        const float* src = Fin + ((size_t)t * NB + b) * (NS * NN);
        float* dst = sm + O_SF(buf);
        #pragma unroll
        for (int m = 0; m < 2; ++m) {
            int idx = m * NTHREADS + tid;
            if (idx < 384) {
                int row = idx / 12, c4 = idx % 12;
                cp16(dst + row * LDF + c4 * 4, src + idx * 4);
            }
        }
        if (tid < 8)
            cp16(sm + O_SFV(buf) + tid * 4, fin + ((size_t)t * NB + b) * NS + tid * 4);
    }
}

// issue cp.async group for forward step t into buffer `buf`
__device__ __forceinline__ void issue_fwd(float* sm, int tid, int t, int b,
                                          const float* Fin, const float* fin,
                                          int buf, bool withF)
{
    if (tid < 128) {
        const float* srcK = g_K + ((size_t)t * NB + b) * (NC * NS);
        int row = tid >> 3, c = tid & 7;
        cp16(sm + O_K2(buf) + row * LDK + c * 4, srcK + tid * 4);
    }
    if (tid < 4)
        cp16(sm + O_KV2(buf) + tid * 4, g_k + ((size_t)t * NB + b) * NC + tid * 4);
    if (withF) {
        const float* src = Fin + ((size_t)t * NB + b) * (NS * NN);
        float* dst = sm + O_SF(buf);
        #pragma unroll
        for (int m = 0; m < 2; ++m) {
            int idx = m * NTHREADS + tid;
            if (idx < 384) {
                int row = idx / 12, c4 = idx % 12;
                cp16(dst + row * LDF + c4 * 4, src + idx * 4);
            }
        }
        if (tid < 8)
            cp16(sm + O_SFV(buf) + tid * 4, fin + ((size_t)t * NB + b) * NS + tid * 4);
    }
}

__global__ __launch_bounds__(NTHREADS, 4)
void lqr_kernel(const float* __restrict__ x0,
                const float* __restrict__ Cin,
                const float* __restrict__ cin,
                const float* __restrict__ Fin,
                const float* __restrict__ fin,
                float* __restrict__ out)
{
    const int b = blockIdx.x;
    const int tid = threadIdx.x;
    const int lane = tid & 31;
    const int warp = tid >> 5;

    __shared__ __align__(16) float sm[SMEM_TOT];

    // =============================== BACKWARD ===============================
    // Prologue: G_term (C49,c49 -> buf1), G_48 (full -> buf0)
    issue_bwd(sm, tid, TT - 1, b, Cin, cin, Fin, fin, 1, false);
    CP_COMMIT();
    issue_bwd(sm, tid, TT - 2, b, Cin, cin, Fin, fin, 0, true);
    CP_COMMIT();
    CP_WAIT(1);
    __syncthreads();

    // terminal factor + p3 (Qm = C49, qv = c49)
    if (warp == 0)
        factor_w0(lane, sm + O_SQ(1), sm + O_SCV(1) + NS, sm + O_SK, sm + O_SKV);
    __syncthreads();
    p3_phase(sm, tid, TT - 1, b, sm + O_SQ(1), sm + O_SCV(1));
    __syncthreads();

    for (int t = TT - 2; t >= 0; --t) {
        const int p = t & 1;
        if (t > 0) {
            issue_bwd(sm, tid, t - 1, b, Cin, cin, Fin, fin, 1 - p, true);
            CP_COMMIT();
            CP_WAIT(1);
        } else {
            CP_WAIT(0);
        }
        __syncthreads(); // B0: step-t data visible; prev p3 writes visible

        float* sQp = sm + O_SQ(p);
        const float* Fp = sm + O_SF(p);
        const float* sV = sm + O_SV;
        float* sW = sm + O_SW;

        // ---- P1: W = V @ F (V symmetric) ---- thread: row i, 6-col group g
        {
            int i = lane, g = warp, j0 = 6 * g;
            float2 a0 = {0.f, 0.f}, a1 = a0, a2 = a0;
            #pragma unroll 8
            for (int s = 0; s < NS; ++s) {
                float v = sV[i * LDV + s];
                float2 f0 = *(const float2*)&Fp[s * LDF + j0];
                float2 f1 = *(const float2*)&Fp[s * LDF + j0 + 2];
                float2 f2 = *(const float2*)&Fp[s * LDF + j0 + 4];
                a0.x += v * f0.x; a0.y += v * f0.y;
                a1.x += v * f1.x; a1.y += v * f1.y;
                a2.x += v * f2.x; a2.y += v * f2.y;
            }
            *(float2*)&sW[i * LDF + j0]     = a0;
            *(float2*)&sW[i * LDF + j0 + 2] = a1;
            *(float2*)&sW[i * LDF + j0 + 4] = a2;
        }
        __syncthreads(); // B1

        // ---- P2: Qm = C + F^T W (192 thr, in-place) ; qv (48 thr) ----
        if (tid < 192) {
            int c4 = tid % 12, r0 = tid / 12;
            float4 q0 = *(const float4*)&sQp[r0 * LDQ + c4 * 4];
            float4 q1 = *(const float4*)&sQp[(r0 + 16) * LDQ + c4 * 4];
            float4 q2 = *(const float4*)&sQp[(r0 + 32) * LDQ + c4 * 4];
            #pragma unroll 8
            for (int s = 0; s < NS; ++s) {
                float4 w = *(const float4*)&sW[s * LDF + c4 * 4];
                float f0 = Fp[s * LDF + r0];
                float f1 = Fp[s * LDF + r0 + 16];
                float f2 = Fp[s * LDF + r0 + 32];
                q0.x += f0 * w.x; q0.y += f0 * w.y; q0.z += f0 * w.z; q0.w += f0 * w.w;
                q1.x += f1 * w.x; q1.y += f1 * w.y; q1.z += f1 * w.z; q1.w += f1 * w.w;
                q2.x += f2 * w.x; q2.y += f2 * w.y; q2.z += f2 * w.z; q2.w += f2 * w.w;
            }
            *(float4*)&sQp[r0 * LDQ + c4 * 4] = q0;
            *(float4*)&sQp[(r0 + 16) * LDQ + c4 * 4] = q1;
            *(float4*)&sQp[(r0 + 32) * LDQ + c4 * 4] = q2;
        } else {
            int j = tid - 192;
            if (j < NN) {
                const float* sv = sm + O_SVV;
                const float* sfv = sm + O_SFV(p);
                float a = sm[O_SCV(p) + j];
                #pragma unroll 8
                for (int s = 0; s < NS; ++s)
                    a += Fp[s * LDF + j] * sv[s] + sW[s * LDF + j] * sfv[s];
                sm[O_SQV + j] = a;
            }
        }
        __syncthreads(); // B2

        if (warp == 0)
            factor_w0(lane, sQp, sm + O_SQV + NS, sm + O_SK, sm + O_SKV);
        __syncthreads(); // B3

        p3_phase(sm, tid, t, b, sQp, sm + O_SQV);
        __syncthreads(); // B4: sV for next P1; buffers free for next issue
    }

    // =============================== FORWARD ================================
    if (tid < NS) sm[O_SX + tid] = x0[(size_t)b * NS + tid];
    issue_fwd(sm, tid, 0, b, Fin, fin, 0, true);
    CP_COMMIT();

    for (int t = 0; t < TT - 1; ++t) {
        const int pf = t & 1;
        issue_fwd(sm, tid, t + 1, b, Fin, fin, 1 - pf, t + 1 < TT - 1);
        CP_COMMIT();
        CP_WAIT(1);
        __syncthreads(); // data + sx visible

        // u = K x + k (warp 0)
        if (warp == 0) {
            const float* sK2 = sm + O_K2(pf);
            int u = lane & 15, h = lane >> 4;
            float acc = 0.0f;
            #pragma unroll
            for (int ii = 0; ii < 16; ++ii)
                acc += sK2[u * LDK + h * 16 + ii] * sm[O_SX + h * 16 + ii];
            acc += __shfl_xor_sync(FULLM, acc, 16);
            if (lane < 16) sm[O_SX + NS + lane] = acc + sm[O_KV2(pf) + lane];
        }
        __syncthreads();

        if (tid < NN) out[((size_t)t * NB + b) * NN + tid] = sm[O_SX + tid];
        if (tid < NS) {
            const float* Fp = sm + O_SF(pf);
            float a = sm[O_SFV(pf) + tid];
            #pragma unroll 8
            for (int j = 0; j < NN; ++j) a += Fp[tid * LDF + j] * sm[O_SX + j];
            sm[O_SX2 + tid] = a;
        }
        __syncthreads();
        if (tid < NS) sm[O_SX + tid] = sm[O_SX2 + tid];
    }

    // final step t = TT-1 (buffer parity 1)
    CP_WAIT(0);
    __syncthreads();
    if (warp == 0) {
        const float* sK2 = sm + O_K2(1);
        int u = lane & 15, h = lane >> 4;
        float acc = 0.0f;
        #pragma unroll
        for (int ii = 0; ii < 16; ++ii)
            acc += sK2[u * LDK + h * 16 + ii] * sm[O_SX + h * 16 + ii];
        acc += __shfl_xor_sync(FULLM, acc, 16);
        if (lane < 16) sm[O_SX + NS + lane] = acc + sm[O_KV2(1) + lane];
    }
    __syncthreads();
    if (tid < NN) out[((size_t)(TT - 1) * NB + b) * NN + tid] = sm[O_SX + tid];
}

extern "C" void kernel_launch(void* const* d_in, const int* in_sizes, int n_in,
                              void* d_out, int out_size) {
    const float *x0 = nullptr, *C = nullptr, *c = nullptr, *F = nullptr, *f = nullptr;
    for (int i = 0; i < n_in; ++i) {
        long long s = in_sizes[i];
        if (s == (long long)TT * NB * NN * NN) C = (const float*)d_in[i];
        else if (s == (long long)TT * NB * NN) c = (const float*)d_in[i];
        else if (s == (long long)(TT - 1) * NB * NS * NN) F = (const float*)d_in[i];
        else if (s == (long long)(TT - 1) * NB * NS) f = (const float*)d_in[i];
        else if (s == (long long)NB * NS) x0 = (const float*)d_in[i];
    }
    float* out = (float*)d_out;
    lqr_kernel<<<NB, NTHREADS>>>(x0, C, c, F, f, out);
}